// round 7
// baseline (speedup 1.0000x reference)
#include <cuda_runtime.h>

#define NN   2048
#define ORD  3
#define PTS  16
#define DIM1 64
#define DIM2 32
#define PL1  32
#define PL2  8
#define LBL  10
#define GRID 760                // 152 SMs x 5 resident blocks: one wave

// Scratch accumulators (zero at module load; self-reset each launch)
__device__ float    g_num[PL2 * DIM2];
__device__ float    g_den[PL2];
__device__ unsigned g_cnt;

__device__ __forceinline__ float fast_tanh(float x) {
    float r;
    asm("tanh.approx.f32 %0, %1;" : "=f"(r) : "f"(x));
    return r;
}

// cos(2*pi*y): exact reduction + even poly through (2*pi*t)^14, max err ~4e-6
__device__ __forceinline__ float cos2pi(float y) {
    float t = y - rintf(y);
    float u = t * t;
    float p = -1.7143907f;
    p = fmaf(p, u,  7.9035539f);
    p = fmaf(p, u, -26.4257337f);
    p = fmaf(p, u,  60.2446418f);
    p = fmaf(p, u, -85.4567987f);
    p = fmaf(p, u,  64.9393940f);
    p = fmaf(p, u, -19.7392088f);
    p = fmaf(p, u,  1.0f);
    return p;
}

__device__ __forceinline__ int bitrev3(int x) {
    return ((x & 1) << 2) | (x & 2) | ((x & 4) >> 2);
}

// ---------------------------------------------------------------------------
// Persistent blocks: 760 blocks (one wave, 5/SM), each handles rows
// r = bid, bid+760, ... Cross-order AND cross-row prefetch keeps LDGs ~900
// compute-cycles ahead of use.
// ---------------------------------------------------------------------------
__global__ __launch_bounds__(256, 5) void k_fused(
    const float* __restrict__ adj, const float* __restrict__ wm,
    const float* __restrict__ w1, const float* __restrict__ b1,
    const float* __restrict__ w2, const float* __restrict__ b2,
    const float* __restrict__ p1, const float* __restrict__ pb1,
    const float* __restrict__ p2, const float* __restrict__ pb2,
    const float* __restrict__ cw, const float* __restrict__ cb,
    float* __restrict__ out) {

    const int tid = threadIdx.x;
    const int warp = tid >> 5, lane = tid & 31;

    __shared__ float s_w [ORD * PTS];
    __shared__ float s_ws[ORD * PTS];
    __shared__ float red[ORD][8][PTS];
    __shared__ float s_ms[ORD * PTS];
    __shared__ float s_h1[DIM1];
    __shared__ float s_h2[DIM2];
    __shared__ float s_ab[PL1];
    __shared__ float s_s[PL2];
    __shared__ unsigned s_last;

    if (tid < ORD * PTS) {
        float w = wm[tid];
        s_w[tid]  = w;
        s_ws[tid] = w * 0.15915494309189535f;
    }
    __syncthreads();

    int r = blockIdx.x;
    // prime the pipeline: row r, order 0
    const float4* nx0 = reinterpret_cast<const float4*>(adj + (size_t)r * NN);
    float4 pf0 = nx0[tid], pf1 = nx0[tid + 256];

    for (; r < NN; r += GRID) {
        // ---- phase 1: characteristic features ----
#pragma unroll
        for (int o = 0; o < ORD; o++) {
            const float4 c0 = pf0, c1 = pf1;

            // prefetch next chunk (next order, or next row's order 0)
            if (o < ORD - 1) {
                const float4* nx = reinterpret_cast<const float4*>(
                    adj + ((size_t)(o + 1) * NN + r) * NN);
                pf0 = nx[tid]; pf1 = nx[tid + 256];
            } else if (r + GRID < NN) {
                const float4* nx = reinterpret_cast<const float4*>(
                    adj + (size_t)(r + GRID) * NN);
                pf0 = nx[tid]; pf1 = nx[tid + 256];
            }

            const float xs[8] = {c0.x, c0.y, c0.z, c0.w, c1.x, c1.y, c1.z, c1.w};

#pragma unroll
            for (int s = 0; s < 2; s++) {
                float w[7], acc[8];
#pragma unroll
                for (int q = 0; q < 7; q++) { w[q] = s_w[o * PTS + s * 8 + q]; acc[q] = 0.f; }
                const float wsp = s_ws[o * PTS + s * 8 + 7];
                acc[7] = 0.f;

#pragma unroll
                for (int e = 0; e < 8; e++) {
                    const float x = xs[e];
#pragma unroll
                    for (int q = 0; q < 7; q++) acc[q] += __cosf(w[q] * x);
                    acc[7] += cos2pi(wsp * x);
                }

                // split-butterfly: 8 accs -> 1 per lane (point = bitrev3(lane&7))
#pragma unroll
                for (int st = 0; st < 3; st++) {
                    const int bit = 1 << st, half = 8 >> (st + 1);
                    const bool hi = lane & bit;
#pragma unroll
                    for (int q = 0; q < 4; q++) {
                        if (q < half) {
                            float send = hi ? acc[q] : acc[q + half];
                            float recv = __shfl_xor_sync(0xffffffffu, send, bit);
                            acc[q] = (hi ? acc[q + half] : acc[q]) + recv;
                        }
                    }
                }
                float v = acc[0];
                v += __shfl_xor_sync(0xffffffffu, v, 8);
                v += __shfl_xor_sync(0xffffffffu, v, 16);
                if (lane < 8) red[o][warp][s * 8 + lane] = v;
            }
        }
        __syncthreads();

        if (tid < ORD * PTS) {
            const int o = tid >> 4, l = tid & 15;
            float s = 0.f;
#pragma unroll
            for (int wz = 0; wz < 8; wz++) s += red[o][wz][l];
            s_ms[o * PTS + (l & 8) + bitrev3(l & 7)] = s * (1.0f / NN);
        }
        __syncthreads();

        // ---- phase 2: per-row MLP chain ----
        if (tid < DIM1) {
            float a = __ldg(b1 + tid);
#pragma unroll
            for (int k = 0; k < ORD * PTS; k++) a = fmaf(s_ms[k], __ldg(w1 + k * DIM1 + tid), a);
            s_h1[tid] = fmaxf(a, 0.f);
        }
        __syncthreads();

        if (tid < DIM2) {
            float a = __ldg(b2 + tid);
#pragma unroll
            for (int k = 0; k < DIM1; k++) a = fmaf(s_h1[k], __ldg(w2 + k * DIM2 + tid), a);
            s_h2[tid] = fmaxf(a, 0.f);
        }
        __syncthreads();

        if (tid < PL1) {
            float a = __ldg(pb1 + tid);
#pragma unroll
            for (int k = 0; k < DIM2; k++) a = fmaf(s_h2[k], __ldg(p1 + k * PL1 + tid), a);
            s_ab[tid] = fast_tanh(a);
        }
        __syncthreads();

        if (tid < PL2) {
            float a = __ldg(pb2 + tid);
#pragma unroll
            for (int k = 0; k < PL1; k++) a = fmaf(s_ab[k], __ldg(p2 + k * PL2 + tid), a);
            s_s[tid] = a;
        }
        __syncthreads();

        // ---- phase 3: pooling contribution via atomics ----
        {
            const int c = tid >> 5, d = tid & 31;
            float e = __expf(s_s[c]);            // |s| small: safe unshifted
            atomicAdd(&g_num[tid], e * s_h2[d]);
            if (d == 0) atomicAdd(&g_den[c], e);
        }

        // ---- phase 4: the block completing the final row does the head ----
        __threadfence();
        __syncthreads();
        if (tid == 0) s_last = (atomicAdd(&g_cnt, 1u) == NN - 1u) ? 1u : 0u;
        __syncthreads();

        if (s_last) {
            __shared__ float part[8][LBL];
            float v = __ldcg(&g_num[tid]) / __ldcg(&g_den[tid >> 5]);
            {
                float p[LBL];
#pragma unroll
                for (int l = 0; l < LBL; l++) p[l] = v * __ldg(cw + tid * LBL + l);
#pragma unroll
                for (int ofs = 16; ofs; ofs >>= 1)
#pragma unroll
                    for (int l = 0; l < LBL; l++)
                        p[l] += __shfl_xor_sync(0xffffffffu, p[l], ofs);
                if (lane == 0) {
#pragma unroll
                    for (int l = 0; l < LBL; l++) part[warp][l] = p[l];
                }
            }
            __syncthreads();

            if (tid < 32) {
                float logit = -1e30f;
                if (tid < LBL) {
                    float a = __ldg(cb + tid);
#pragma unroll
                    for (int wz = 0; wz < 8; wz++) a += part[wz][tid];
                    logit = a;
                }
                float m2 = logit;
#pragma unroll
                for (int ofs = 16; ofs; ofs >>= 1)
                    m2 = fmaxf(m2, __shfl_xor_sync(0xffffffffu, m2, ofs));
                float ex = (tid < LBL) ? expf(logit - m2) : 0.f;
                float s2 = ex;
#pragma unroll
                for (int ofs = 16; ofs; ofs >>= 1)
                    s2 += __shfl_xor_sync(0xffffffffu, s2, ofs);
                if (tid < LBL) out[tid] = logit - m2 - logf(s2);
            }
            __syncthreads();

            // reset for next graph replay (all contributions & reads done)
            __stcg(&g_num[tid], 0.f);
            if (tid < PL2) __stcg(&g_den[tid], 0.f);
            if (tid == 0) { __threadfence(); atomicExch(&g_cnt, 0u); }
            return;   // provably this block's last row
        }
        __syncthreads();   // shared buffers safe to reuse for next row
    }
}

// ---------------------------------------------------------------------------
extern "C" void kernel_launch(void* const* d_in, const int* in_sizes, int n_in,
                              void* d_out, int out_size) {
    const float* adj = (const float*)d_in[0];
    const float* wm  = (const float*)d_in[1];
    const float* w1  = (const float*)d_in[2];
    const float* b1  = (const float*)d_in[3];
    const float* w2  = (const float*)d_in[4];
    const float* b2  = (const float*)d_in[5];
    const float* p1  = (const float*)d_in[6];
    const float* pb1 = (const float*)d_in[7];
    const float* p2  = (const float*)d_in[8];
    const float* pb2 = (const float*)d_in[9];
    const float* cw  = (const float*)d_in[10];
    const float* cb  = (const float*)d_in[11];
    float* out = (float*)d_out;

    k_fused<<<GRID, 256>>>(adj, wm, w1, b1, w2, b2, p1, pb1, p2, pb2, cw, cb, out);
}